// round 2
// baseline (speedup 1.0000x reference)
#include <cuda_runtime.h>
#include <cstdint>

#define BB 256
#define SS 512
#define N_IN 2048
#define N_OUT 512
#define HH 30
#define ROWS (BB*SS)   // 131072

typedef unsigned long long u64;

// ---------------- f32x2 packed helpers ----------------
__device__ __forceinline__ u64 pk2(float lo, float hi) {
    u64 r; asm("mov.b64 %0,{%1,%2};" : "=l"(r) : "f"(lo), "f"(hi)); return r;
}
__device__ __forceinline__ void upk2(u64 v, float& lo, float& hi) {
    asm("mov.b64 {%0,%1},%2;" : "=f"(lo), "=f"(hi) : "l"(v));
}
__device__ __forceinline__ void ffma2(u64& d, u64 a, u64 b) {
    asm("fma.rn.f32x2 %0,%1,%2,%0;" : "+l"(d) : "l"(a), "l"(b));
}
__device__ __forceinline__ float htanh(float x) {
    float r; asm("tanh.approx.f32 %0,%1;" : "=f"(r) : "f"(x)); return r;
}
__device__ __forceinline__ float hsig(float x) {
    return fmaf(htanh(x * 0.5f), 0.5f, 0.5f);
}

// ---------------- device scratch ----------------
__device__ float g_flat[(size_t)ROWS * HH];
__device__ float g_partial[512 * 64];
__device__ float g_mu[HH];
__device__ float g_rstd[HH];

// ---------------- fc1: [131072,2048] @ [2048,30] + ReLU + BN partials --------
#define FC1_TM 256
#define FC1_KC 16

__global__ __launch_bounds__(256)
void fc1_kernel(const float* __restrict__ x, const float* __restrict__ W1,
                const float* __restrict__ b1)
{
    __shared__ __align__(16) float xs[FC1_KC][FC1_TM];   // 16 KB
    __shared__ __align__(16) u64   ws2[FC1_KC][32];      // 4 KB, (w,w) pairs
    __shared__ float red[2][32][33];                     // 8.4 KB

    const int tid = threadIdx.x;          // 0..255
    const int rg  = tid >> 3;             // 0..31
    const int cg  = tid & 7;              // 0..7
    const int r0  = rg * 8;
    const int c0  = cg * 4;               // cols c0..c0+3 (pad cols 30,31 zero)
    const size_t rowBase = (size_t)blockIdx.x * FC1_TM;

    u64 acc[4][4];                        // [rowpair][col]
    #pragma unroll
    for (int p = 0; p < 4; p++)
        #pragma unroll
        for (int j = 0; j < 4; j++) acc[p][j] = 0ULL;

    for (int kc = 0; kc < N_IN; kc += FC1_KC) {
        for (int i = tid; i < FC1_TM * FC1_KC / 4; i += 256) {
            int r  = i >> 2;
            int k4 = i & 3;
            float4 v = *(const float4*)&x[(rowBase + r) * (size_t)N_IN + kc + k4 * 4];
            xs[k4*4+0][r] = v.x; xs[k4*4+1][r] = v.y;
            xs[k4*4+2][r] = v.z; xs[k4*4+3][r] = v.w;
        }
        for (int i = tid; i < FC1_KC * 32; i += 256) {
            int k = i >> 5, c = i & 31;
            float w = (c < HH) ? W1[(size_t)(kc + k) * HH + c] : 0.f;
            ws2[k][c] = pk2(w, w);
        }
        __syncthreads();
        #pragma unroll
        for (int k = 0; k < FC1_KC; k++) {
            ulonglong2 xa = *(const ulonglong2*)&xs[k][r0];
            ulonglong2 xb = *(const ulonglong2*)&xs[k][r0 + 4];
            ulonglong2 wa = *(const ulonglong2*)&ws2[k][c0];
            ulonglong2 wb = *(const ulonglong2*)&ws2[k][c0 + 2];
            u64 xp[4] = {xa.x, xa.y, xb.x, xb.y};
            u64 wp[4] = {wa.x, wa.y, wb.x, wb.y};
            #pragma unroll
            for (int p = 0; p < 4; p++)
                #pragma unroll
                for (int j = 0; j < 4; j++) ffma2(acc[p][j], xp[p], wp[j]);
        }
        __syncthreads();
    }

    // bias + ReLU + store + BN partials
    float bloc[4];
    #pragma unroll
    for (int j = 0; j < 4; j++) bloc[j] = (c0 + j < HH) ? b1[c0 + j] : 0.f;
    float psum[4] = {0,0,0,0}, psq[4] = {0,0,0,0};
    #pragma unroll
    for (int p = 0; p < 4; p++) {
        size_t row = rowBase + r0 + 2 * p;
        #pragma unroll
        for (int j = 0; j < 4; j++) {
            float lo, hi;
            upk2(acc[p][j], lo, hi);
            float v0 = fmaxf(lo + bloc[j], 0.f);
            float v1 = fmaxf(hi + bloc[j], 0.f);
            if (c0 + j < HH) {
                g_flat[row * HH + c0 + j]       = v0;
                g_flat[(row + 1) * HH + c0 + j] = v1;
            }
            psum[j] += v0 + v1;
            psq[j]  += v0 * v0 + v1 * v1;
        }
    }
    #pragma unroll
    for (int j = 0; j < 4; j++) {
        red[0][c0 + j][rg] = psum[j];
        red[1][c0 + j][rg] = psq[j];
    }
    __syncthreads();
    if (tid < HH) {
        float s = 0.f, q = 0.f;
        #pragma unroll 8
        for (int g = 0; g < 32; g++) { s += red[0][tid][g]; q += red[1][tid][g]; }
        g_partial[blockIdx.x * 60 + tid]      = s;
        g_partial[blockIdx.x * 60 + 30 + tid] = q;
    }
}

// ---------------- BN finalize ----------------
__global__ void bn_stats_kernel()
{
    __shared__ float rs[2][HH][9];
    int c = threadIdx.x & 31;
    int g = threadIdx.x >> 5;   // 0..7
    if (c < HH) {
        float s = 0.f, q = 0.f;
        for (int p = g; p < 512; p += 8) {
            s += g_partial[p * 60 + c];
            q += g_partial[p * 60 + 30 + c];
        }
        rs[0][c][g] = s; rs[1][c][g] = q;
    }
    __syncthreads();
    if (threadIdx.x < HH) {
        float s = 0.f, q = 0.f;
        #pragma unroll
        for (int g2 = 0; g2 < 8; g2++) { s += rs[0][threadIdx.x][g2]; q += rs[1][threadIdx.x][g2]; }
        const float n = (float)ROWS;
        float mu  = s / n;
        float var = q / n - mu * mu;
        g_mu[threadIdx.x]   = mu;
        g_rstd[threadIdx.x] = rsqrtf(var + 1e-5f);
    }
}

// ---------------- LSTM ----------------
#define LSTM_THREADS 256
#define LSTM_SMEM_FLOATS (SS*32 + 32 + 32 + 32 + 128 + 128 + 32 + 32)
#define LSTM_SMEM_BYTES  (LSTM_SMEM_FLOATS * 4)

__device__ __forceinline__ float dot2(const float* __restrict__ xv,
                                      const float* __restrict__ hv,
                                      const u64 (&wi)[16], const u64 (&wh)[16],
                                      float bj)
{
    u64 a0 = 0ULL, a1 = 0ULL, a2 = 0ULL, a3 = 0ULL;
    const ulonglong2* x2 = (const ulonglong2*)xv;
    const ulonglong2* h2 = (const ulonglong2*)hv;
    #pragma unroll
    for (int q = 0; q < 8; q++) {
        ulonglong2 xq = x2[q];
        ffma2(a0, xq.x, wi[2*q]);
        ffma2(a1, xq.y, wi[2*q+1]);
    }
    #pragma unroll
    for (int q = 0; q < 8; q++) {
        ulonglong2 hq = h2[q];
        ffma2(a2, hq.x, wh[2*q]);
        ffma2(a3, hq.y, wh[2*q+1]);
    }
    float s0,s1,s2,s3,s4,s5,s6,s7;
    upk2(a0,s0,s1); upk2(a1,s2,s3); upk2(a2,s4,s5); upk2(a3,s6,s7);
    return bj + (((s0+s1)+(s2+s3)) + ((s4+s5)+(s6+s7)));
}

__global__ __launch_bounds__(LSTM_THREADS, 2)
void lstm_kernel(const float* __restrict__ h0, const float* __restrict__ c0,
                 const float* __restrict__ Wih0, const float* __restrict__ Whh0,
                 const float* __restrict__ bias0,
                 const float* __restrict__ Wih1, const float* __restrict__ Whh1,
                 const float* __restrict__ bias1,
                 float* __restrict__ rnn_out)
{
    extern __shared__ __align__(16) float lsm[];
    float* xs    = lsm;                    // [512][32]
    float* h0s   = lsm + SS * 32;          // [32]
    float* h1s   = h0s + 32;               // [32]
    float* y0s   = h1s + 32;               // [32]
    float* z0s   = y0s + 32;               // [128]
    float* z1s   = z0s + 128;              // [128]
    float* mus   = z1s + 128;              // [32]
    float* rstds = mus + 32;               // [32]

    const int tid = threadIdx.x;
    const int b   = blockIdx.x;

    if (tid < 32) {
        mus[tid]   = (tid < HH) ? g_mu[tid]   : 0.f;
        rstds[tid] = (tid < HH) ? g_rstd[tid] : 0.f;
        h0s[tid] = (tid < HH) ? h0[b * HH + tid]            : 0.f;
        h1s[tid] = (tid < HH) ? h0[BB * HH + b * HH + tid]  : 0.f;
        y0s[tid] = 0.f;
    }
    __syncthreads();

    const float* fb = g_flat + (size_t)b * (SS * HH);
    for (int i = tid; i < SS * 32; i += LSTM_THREADS) {
        int s = i >> 5, k = i & 31;
        xs[i] = (k < HH) ? (fb[s * HH + k] - mus[k]) * rstds[k] : 0.f;
    }

    u64 wi[16], wh[16];
    float bj = 0.f;
    #pragma unroll
    for (int k = 0; k < 16; k++) { wi[k] = 0ULL; wh[k] = 0ULL; }
    if (tid < 120) {
        #pragma unroll
        for (int p = 0; p < 15; p++) {
            wi[p] = pk2(Wih0[tid * HH + 2*p], Wih0[tid * HH + 2*p + 1]);
            wh[p] = pk2(Whh0[tid * HH + 2*p], Whh0[tid * HH + 2*p + 1]);
        }
        bj = bias0[tid];
    } else if (tid >= 128 && tid < 248) {
        int j = tid - 128;
        #pragma unroll
        for (int p = 0; p < 15; p++) {
            wi[p] = pk2(Wih1[j * HH + 2*p], Wih1[j * HH + 2*p + 1]);
            wh[p] = pk2(Whh1[j * HH + 2*p], Whh1[j * HH + 2*p + 1]);
        }
        bj = bias1[j];
    }

    float creg = 0.f;
    if (tid < HH)                          creg = c0[b * HH + tid];
    else if (tid >= 128 && tid < 128+HH)   creg = c0[BB * HH + b * HH + (tid - 128)];

    __syncthreads();

    for (int t = 0; t <= SS; t++) {
        if (t < SS && tid < 120) {
            z0s[tid] = dot2(xs + t * 32, h0s, wi, wh, bj);
        } else if (t >= 1 && tid >= 128 && tid < 248) {
            z1s[tid - 128] = dot2(y0s, h1s, wi, wh, bj);
        }
        __syncthreads();
        if (t < SS && tid < HH) {
            float ig = hsig(z0s[tid]);
            float fg = hsig(z0s[30 + tid]);
            float gg = htanh(z0s[60 + tid]);
            float og = hsig(z0s[90 + tid]);
            creg = fg * creg + ig * gg;
            float hh = og * htanh(creg);
            h0s[tid] = hh;
            y0s[tid] = hh;
        } else if (t >= 1 && tid >= 128 && tid < 128 + HH) {
            int u = tid - 128;
            float ig = hsig(z1s[u]);
            float fg = hsig(z1s[30 + u]);
            float gg = htanh(z1s[60 + u]);
            float og = hsig(z1s[90 + u]);
            creg = fg * creg + ig * gg;
            float hh = og * htanh(creg);
            h1s[u] = hh;
            rnn_out[((size_t)b * SS + (t - 1)) * HH + u] = hh;
        }
        __syncthreads();
    }
}

// ---------------- output GEMM: [131072,30] @ [30,512] + bias ----------------
#define OG_TM 64
#define OG_TN 256

__global__ __launch_bounds__(256)
void out_kernel(const float* __restrict__ rnn, const float* __restrict__ Wout,
                const float* __restrict__ bout, float* __restrict__ dorsal)
{
    __shared__ __align__(16) float ws[HH][OG_TN];     // 30 KB
    __shared__ __align__(16) u64   ins2[HH][OG_TM];   // 15 KB, (v,v) pairs

    const int tid = threadIdx.x;
    const int cb  = (blockIdx.x & 1) * OG_TN;
    const size_t rowBase = (size_t)(blockIdx.x >> 1) * OG_TM;

    for (int i = tid; i < HH * OG_TN; i += 256) {
        int k = i >> 8, c = i & 255;
        ws[k][c] = Wout[(size_t)k * N_OUT + cb + c];
    }
    for (int i = tid; i < OG_TM * HH; i += 256) {
        int r = i / HH, k = i % HH;
        float v = rnn[(rowBase + r) * HH + k];
        ins2[k][r] = pk2(v, v);
    }

    const int rg = tid >> 5;     // 0..7
    const int cg = tid & 31;     // 0..31
    const int r0 = rg * 8, c0 = cg * 8;

    u64 acc[8][4];               // 8 rows x 4 col-pairs
    #pragma unroll
    for (int j = 0; j < 4; j++) {
        u64 bp = pk2(bout[cb + c0 + 2*j], bout[cb + c0 + 2*j + 1]);
        #pragma unroll
        for (int i = 0; i < 8; i++) acc[i][j] = bp;
    }

    __syncthreads();

    #pragma unroll
    for (int k = 0; k < HH; k++) {
        ulonglong2 i01 = *(const ulonglong2*)&ins2[k][r0];
        ulonglong2 i23 = *(const ulonglong2*)&ins2[k][r0 + 2];
        ulonglong2 i45 = *(const ulonglong2*)&ins2[k][r0 + 4];
        ulonglong2 i67 = *(const ulonglong2*)&ins2[k][r0 + 6];
        u64 iv[8] = {i01.x, i01.y, i23.x, i23.y, i45.x, i45.y, i67.x, i67.y};
        ulonglong2 w01 = *(const ulonglong2*)&ws[k][c0];
        ulonglong2 w23 = *(const ulonglong2*)&ws[k][c0 + 4];
        u64 wp[4] = {w01.x, w01.y, w23.x, w23.y};
        #pragma unroll
        for (int i = 0; i < 8; i++)
            #pragma unroll
            for (int j = 0; j < 4; j++) ffma2(acc[i][j], iv[i], wp[j]);
    }

    #pragma unroll
    for (int i = 0; i < 8; i++) {
        size_t row = rowBase + r0 + i;
        float o[8];
        #pragma unroll
        for (int j = 0; j < 4; j++) upk2(acc[i][j], o[2*j], o[2*j+1]);
        float4* dp = (float4*)&dorsal[row * N_OUT + cb + c0];
        dp[0] = make_float4(o[0], o[1], o[2], o[3]);
        dp[1] = make_float4(o[4], o[5], o[6], o[7]);
    }
}

// ---------------- launch ----------------
extern "C" void kernel_launch(void* const* d_in, const int* in_sizes, int n_in,
                              void* d_out, int out_size)
{
    const float* x     = (const float*)d_in[0];
    const float* h0    = (const float*)d_in[1];
    const float* c0    = (const float*)d_in[2];
    const float* W1    = (const float*)d_in[3];
    const float* b1    = (const float*)d_in[4];
    const float* Wih0  = (const float*)d_in[5];
    const float* Whh0  = (const float*)d_in[6];
    const float* bias0 = (const float*)d_in[7];
    const float* Wih1  = (const float*)d_in[8];
    const float* Whh1  = (const float*)d_in[9];
    const float* bias1 = (const float*)d_in[10];
    const float* Wout  = (const float*)d_in[11];
    const float* bout  = (const float*)d_in[12];

    float* out    = (float*)d_out;
    float* dorsal = out;
    float* rnn    = out + (size_t)ROWS * N_OUT;

    cudaFuncSetAttribute(lstm_kernel, cudaFuncAttributeMaxDynamicSharedMemorySize,
                         LSTM_SMEM_BYTES);

    fc1_kernel<<<ROWS / FC1_TM, 256>>>(x, W1, b1);
    bn_stats_kernel<<<1, 256>>>();
    lstm_kernel<<<BB, LSTM_THREADS, LSTM_SMEM_BYTES>>>(h0, c0, Wih0, Whh0, bias0,
                                                       Wih1, Whh1, bias1, rnn);
    out_kernel<<<(ROWS / OG_TM) * 2, 256>>>(rnn, Wout, bout, dorsal);
}

// round 4
// speedup vs baseline: 1.7210x; 1.7210x over previous
#include <cuda_runtime.h>
#include <cstdint>

#define BB 256
#define SS 512
#define N_IN 2048
#define N_OUT 512
#define HH 30
#define ROWS (BB*SS)   // 131072

// ---------------- device scratch ----------------
__device__ float g_flat[(size_t)ROWS * HH];
__device__ float g_partial[1024 * 64];
__device__ float g_mu[HH];
__device__ float g_rstd[HH];

// ---------------- helpers ----------------
__device__ __forceinline__ uint32_t cvt_tf32(float f) {
    uint32_t u; asm("cvt.rna.tf32.f32 %0, %1;" : "=r"(u) : "f"(f)); return u;
}
__device__ __forceinline__ void mma_tf32(float& c0, float& c1, float& c2, float& c3,
                                         uint32_t a0, uint32_t a1, uint32_t a2, uint32_t a3,
                                         uint32_t b0, uint32_t b1) {
    asm volatile(
        "mma.sync.aligned.m16n8k8.row.col.f32.tf32.tf32.f32 "
        "{%0,%1,%2,%3},{%4,%5,%6,%7},{%8,%9},{%0,%1,%2,%3};"
        : "+f"(c0), "+f"(c1), "+f"(c2), "+f"(c3)
        : "r"(a0), "r"(a1), "r"(a2), "r"(a3), "r"(b0), "r"(b1));
}
__device__ __forceinline__ float htanh(float x) {
    float r; asm("tanh.approx.f32 %0,%1;" : "=f"(r) : "f"(x)); return r;
}
__device__ __forceinline__ float hsig(float x) {
    return fmaf(htanh(x * 0.5f), 0.5f, 0.5f);
}

// ================= fc1: tf32 mma.sync GEMM =================
// C[131072,30] = X[131072,2048] @ W1[2048,30]; +bias, ReLU, BN partials.
// Block: 256 thr (8 warps), M_TILE=128 (m16/warp), N=32 pad, KC=32 per chunk.
__global__ __launch_bounds__(256)
void fc1_mma_kernel(const float* __restrict__ x, const float* __restrict__ W1,
                    const float* __restrict__ b1)
{
    __shared__ float a_s[128][36];          // x chunk (tf32 bits as float)
    __shared__ float bh_s[32][36];          // W hi, [n][k]
    __shared__ float bl_s[32][36];          // W lo, [n][k]
    __shared__ float red[2][32][8];
    __shared__ float bias_s[32];

    const int tid  = threadIdx.x;
    const int wid  = tid >> 5;
    const int lane = tid & 31;
    const int g    = lane >> 2;     // 0..7
    const int tg   = lane & 3;      // 0..3
    const size_t rowBase = (size_t)blockIdx.x * 128;

    if (tid < 32) bias_s[tid] = (tid < HH) ? b1[tid] : 0.f;

    float c[4][4];
    #pragma unroll
    for (int nt = 0; nt < 4; nt++)
        #pragma unroll
        for (int q = 0; q < 4; q++) c[nt][q] = 0.f;

    // prefetch chunk 0
    float4 pf[4];
    #pragma unroll
    for (int q = 0; q < 4; q++) {
        int idx = q * 256 + tid, r = idx >> 3, kq = idx & 7;
        pf[q] = *(const float4*)&x[(rowBase + r) * (size_t)N_IN + kq * 4];
    }

    for (int j = 0; j < 64; j++) {
        // store A chunk (tf32-rounded)
        #pragma unroll
        for (int q = 0; q < 4; q++) {
            int idx = q * 256 + tid, r = idx >> 3, kq = idx & 7;
            a_s[r][kq*4+0] = __uint_as_float(cvt_tf32(pf[q].x));
            a_s[r][kq*4+1] = __uint_as_float(cvt_tf32(pf[q].y));
            a_s[r][kq*4+2] = __uint_as_float(cvt_tf32(pf[q].z));
            a_s[r][kq*4+3] = __uint_as_float(cvt_tf32(pf[q].w));
        }
        // W chunk, hi/lo split, stored [n][k]
        #pragma unroll
        for (int i = tid; i < 1024; i += 256) {
            int k = i >> 5, n = i & 31;
            float w = (n < HH) ? W1[(size_t)(j * 32 + k) * HH + n] : 0.f;
            uint32_t hb = cvt_tf32(w);
            float lo = w - __uint_as_float(hb);
            bh_s[n][k] = __uint_as_float(hb);
            bl_s[n][k] = __uint_as_float(cvt_tf32(lo));
        }
        __syncthreads();
        // prefetch next chunk
        if (j < 63) {
            #pragma unroll
            for (int q = 0; q < 4; q++) {
                int idx = q * 256 + tid, r = idx >> 3, kq = idx & 7;
                pf[q] = *(const float4*)&x[(rowBase + r) * (size_t)N_IN + (j + 1) * 32 + kq * 4];
            }
        }
        // MMAs
        const int mr = wid * 16;
        #pragma unroll
        for (int ks = 0; ks < 4; ks++) {
            const int k0 = ks * 8;
            uint32_t a0 = __float_as_uint(a_s[mr + g    ][k0 + tg    ]);
            uint32_t a1 = __float_as_uint(a_s[mr + g + 8][k0 + tg    ]);
            uint32_t a2 = __float_as_uint(a_s[mr + g    ][k0 + tg + 4]);
            uint32_t a3 = __float_as_uint(a_s[mr + g + 8][k0 + tg + 4]);
            #pragma unroll
            for (int nt = 0; nt < 4; nt++) {
                uint32_t bh0 = __float_as_uint(bh_s[nt*8 + g][k0 + tg    ]);
                uint32_t bh1 = __float_as_uint(bh_s[nt*8 + g][k0 + tg + 4]);
                mma_tf32(c[nt][0], c[nt][1], c[nt][2], c[nt][3], a0, a1, a2, a3, bh0, bh1);
                uint32_t bl0 = __float_as_uint(bl_s[nt*8 + g][k0 + tg    ]);
                uint32_t bl1 = __float_as_uint(bl_s[nt*8 + g][k0 + tg + 4]);
                mma_tf32(c[nt][0], c[nt][1], c[nt][2], c[nt][3], a0, a1, a2, a3, bl0, bl1);
            }
        }
        __syncthreads();
    }

    // epilogue: bias + ReLU + store + BN partials
    size_t r0 = rowBase + wid * 16 + g;
    size_t r1 = r0 + 8;
    #pragma unroll
    for (int nt = 0; nt < 4; nt++) {
        int col = nt * 8 + tg * 2;
        float v00 = 0.f, v01 = 0.f, v10 = 0.f, v11 = 0.f;
        if (col < HH) {
            v00 = fmaxf(c[nt][0] + bias_s[col],     0.f);
            v01 = fmaxf(c[nt][1] + bias_s[col + 1], 0.f);
            v10 = fmaxf(c[nt][2] + bias_s[col],     0.f);
            v11 = fmaxf(c[nt][3] + bias_s[col + 1], 0.f);
            *(float2*)&g_flat[r0 * HH + col] = make_float2(v00, v01);
            *(float2*)&g_flat[r1 * HH + col] = make_float2(v10, v11);
        }
        float s0 = v00 + v10, q0 = v00 * v00 + v10 * v10;
        float s1 = v01 + v11, q1 = v01 * v01 + v11 * v11;
        #pragma unroll
        for (int off = 4; off < 32; off <<= 1) {
            s0 += __shfl_xor_sync(0xffffffffu, s0, off);
            q0 += __shfl_xor_sync(0xffffffffu, q0, off);
            s1 += __shfl_xor_sync(0xffffffffu, s1, off);
            q1 += __shfl_xor_sync(0xffffffffu, q1, off);
        }
        if (g == 0) {
            red[0][col][wid]     = s0;
            red[0][col + 1][wid] = s1;
            red[1][col][wid]     = q0;
            red[1][col + 1][wid] = q1;
        }
    }
    __syncthreads();
    if (tid < HH) {
        float s = 0.f, q = 0.f;
        #pragma unroll
        for (int w = 0; w < 8; w++) { s += red[0][tid][w]; q += red[1][tid][w]; }
        g_partial[blockIdx.x * 60 + tid]      = s;
        g_partial[blockIdx.x * 60 + 30 + tid] = q;
    }
}

// ---------------- BN finalize ----------------
__global__ void bn_stats_kernel()
{
    __shared__ float rs[2][HH][9];
    int c = threadIdx.x & 31;
    int g = threadIdx.x >> 5;   // 0..7
    if (c < HH) {
        float s = 0.f, q = 0.f;
        for (int p = g; p < 1024; p += 8) {
            s += g_partial[p * 60 + c];
            q += g_partial[p * 60 + 30 + c];
        }
        rs[0][c][g] = s; rs[1][c][g] = q;
    }
    __syncthreads();
    if (threadIdx.x < HH) {
        float s = 0.f, q = 0.f;
        #pragma unroll
        for (int g2 = 0; g2 < 8; g2++) { s += rs[0][threadIdx.x][g2]; q += rs[1][threadIdx.x][g2]; }
        const float n = (float)ROWS;
        float mu  = s / n;
        float var = q / n - mu * mu;
        g_mu[threadIdx.x]   = mu;
        g_rstd[threadIdx.x] = rsqrtf(var + 1e-5f);
    }
}

// ---------------- LSTM (scalar + MUFU tanh) ----------------
#define LSTM_THREADS 256
#define LSTM_SMEM_FLOATS (SS*32 + 32 + 32 + 32 + 128 + 128 + 32 + 32)
#define LSTM_SMEM_BYTES  (LSTM_SMEM_FLOATS * 4)

__device__ __forceinline__ float dot_step(const float* __restrict__ xv,
                                          const float* __restrict__ hv,
                                          const float (&wi)[32], const float (&wh)[32],
                                          float bj)
{
    const float4* x4 = (const float4*)xv;
    const float4* h4 = (const float4*)hv;
    float a0 = bj, a1 = 0.f, a2 = 0.f, a3 = 0.f;
    #pragma unroll
    for (int q = 0; q < 8; q++) {
        float4 xq = x4[q];
        a0 += wi[4*q+0] * xq.x; a1 += wi[4*q+1] * xq.y;
        a2 += wi[4*q+2] * xq.z; a3 += wi[4*q+3] * xq.w;
    }
    #pragma unroll
    for (int q = 0; q < 8; q++) {
        float4 hq = h4[q];
        a0 += wh[4*q+0] * hq.x; a1 += wh[4*q+1] * hq.y;
        a2 += wh[4*q+2] * hq.z; a3 += wh[4*q+3] * hq.w;
    }
    return (a0 + a1) + (a2 + a3);
}

__global__ __launch_bounds__(LSTM_THREADS, 2)
void lstm_kernel(const float* __restrict__ h0, const float* __restrict__ c0,
                 const float* __restrict__ Wih0, const float* __restrict__ Whh0,
                 const float* __restrict__ bias0,
                 const float* __restrict__ Wih1, const float* __restrict__ Whh1,
                 const float* __restrict__ bias1,
                 float* __restrict__ rnn_out)
{
    extern __shared__ __align__(16) float lsm[];
    float* xs    = lsm;                    // [512][32]
    float* h0s   = lsm + SS * 32;          // [32]
    float* h1s   = h0s + 32;               // [32]
    float* y0s   = h1s + 32;               // [32]
    float* z0s   = y0s + 32;               // [128]
    float* z1s   = z0s + 128;              // [128]
    float* mus   = z1s + 128;              // [32]
    float* rstds = mus + 32;               // [32]

    const int tid = threadIdx.x;
    const int b   = blockIdx.x;

    if (tid < 32) {
        mus[tid]   = (tid < HH) ? g_mu[tid]   : 0.f;
        rstds[tid] = (tid < HH) ? g_rstd[tid] : 0.f;
        h0s[tid] = (tid < HH) ? h0[b * HH + tid]            : 0.f;
        h1s[tid] = (tid < HH) ? h0[BB * HH + b * HH + tid]  : 0.f;
        y0s[tid] = 0.f;
    }
    __syncthreads();

    const float* fb = g_flat + (size_t)b * (SS * HH);
    for (int i = tid; i < SS * 32; i += LSTM_THREADS) {
        int s = i >> 5, k = i & 31;
        xs[i] = (k < HH) ? (fb[s * HH + k] - mus[k]) * rstds[k] : 0.f;
    }

    float wi[32], wh[32];
    float bj = 0.f;
    #pragma unroll
    for (int k = 0; k < 32; k++) { wi[k] = 0.f; wh[k] = 0.f; }
    if (tid < 120) {
        #pragma unroll
        for (int k = 0; k < HH; k++) {
            wi[k] = Wih0[tid * HH + k];
            wh[k] = Whh0[tid * HH + k];
        }
        bj = bias0[tid];
    } else if (tid >= 128 && tid < 248) {
        int j = tid - 128;
        #pragma unroll
        for (int k = 0; k < HH; k++) {
            wi[k] = Wih1[j * HH + k];
            wh[k] = Whh1[j * HH + k];
        }
        bj = bias1[j];
    }

    float creg = 0.f;
    if (tid < HH)                          creg = c0[b * HH + tid];
    else if (tid >= 128 && tid < 128+HH)   creg = c0[BB * HH + b * HH + (tid - 128)];

    __syncthreads();

    for (int t = 0; t <= SS; t++) {
        if (t < SS && tid < 120) {
            z0s[tid] = dot_step(xs + t * 32, h0s, wi, wh, bj);
        } else if (t >= 1 && tid >= 128 && tid < 248) {
            z1s[tid - 128] = dot_step(y0s, h1s, wi, wh, bj);
        }
        __syncthreads();
        if (t < SS && tid < HH) {
            float ig = hsig(z0s[tid]);
            float fg = hsig(z0s[30 + tid]);
            float gg = htanh(z0s[60 + tid]);
            float og = hsig(z0s[90 + tid]);
            creg = fg * creg + ig * gg;
            float hh = og * htanh(creg);
            h0s[tid] = hh;
            y0s[tid] = hh;
        } else if (t >= 1 && tid >= 128 && tid < 128 + HH) {
            int u = tid - 128;
            float ig = hsig(z1s[u]);
            float fg = hsig(z1s[30 + u]);
            float gg = htanh(z1s[60 + u]);
            float og = hsig(z1s[90 + u]);
            creg = fg * creg + ig * gg;
            float hh = og * htanh(creg);
            h1s[u] = hh;
            rnn_out[((size_t)b * SS + (t - 1)) * HH + u] = hh;
        }
        __syncthreads();
    }
}

// ================= output GEMM: tf32 mma.sync =================
// dorsal[131072,512] = rnn[131072,30] @ Wout[30,512] + bout
// Block: 256 thr, tile 128 rows x 64 cols. grid = (M/128)*(N/64).
__global__ __launch_bounds__(256)
void out_mma_kernel(const float* __restrict__ rnn, const float* __restrict__ Wout,
                    const float* __restrict__ bout, float* __restrict__ dorsal)
{
    __shared__ float a_s[128][36];
    __shared__ float bh_s[64][36];
    __shared__ float bl_s[64][36];

    const int tid  = threadIdx.x;
    const int wid  = tid >> 5;
    const int lane = tid & 31;
    const int g    = lane >> 2;
    const int tg   = lane & 3;
    const size_t rb = (size_t)(blockIdx.x >> 3) * 128;
    const int cb    = (blockIdx.x & 7) * 64;

    // A: rnn rows, k padded 30->32
    for (int i = tid; i < 128 * 32; i += 256) {
        int r = i >> 5, k = i & 31;
        float v = (k < HH) ? rnn[(rb + r) * HH + k] : 0.f;
        a_s[r][k] = __uint_as_float(cvt_tf32(v));
    }
    // B: Wout[k][cb+n] hi/lo, stored [n][k]
    for (int i = tid; i < 64 * 32; i += 256) {
        int k = i >> 6, n = i & 63;
        float w = (k < HH) ? Wout[(size_t)k * N_OUT + cb + n] : 0.f;
        uint32_t hb = cvt_tf32(w);
        bh_s[n][k] = __uint_as_float(hb);
        bl_s[n][k] = __uint_as_float(cvt_tf32(w - __uint_as_float(hb)));
    }

    float c[8][4];
    #pragma unroll
    for (int nt = 0; nt < 8; nt++) {
        float bv0 = bout[cb + nt * 8 + tg * 2];
        float bv1 = bout[cb + nt * 8 + tg * 2 + 1];
        c[nt][0] = bv0; c[nt][1] = bv1; c[nt][2] = bv0; c[nt][3] = bv1;
    }
    __syncthreads();

    const int mr = wid * 16;
    #pragma unroll
    for (int ks = 0; ks < 4; ks++) {
        const int k0 = ks * 8;
        uint32_t a0 = __float_as_uint(a_s[mr + g    ][k0 + tg    ]);
        uint32_t a1 = __float_as_uint(a_s[mr + g + 8][k0 + tg    ]);
        uint32_t a2 = __float_as_uint(a_s[mr + g    ][k0 + tg + 4]);
        uint32_t a3 = __float_as_uint(a_s[mr + g + 8][k0 + tg + 4]);
        #pragma unroll
        for (int nt = 0; nt < 8; nt++) {
            uint32_t bh0 = __float_as_uint(bh_s[nt*8 + g][k0 + tg    ]);
            uint32_t bh1 = __float_as_uint(bh_s[nt*8 + g][k0 + tg + 4]);
            mma_tf32(c[nt][0], c[nt][1], c[nt][2], c[nt][3], a0, a1, a2, a3, bh0, bh1);
            uint32_t bl0 = __float_as_uint(bl_s[nt*8 + g][k0 + tg    ]);
            uint32_t bl1 = __float_as_uint(bl_s[nt*8 + g][k0 + tg + 4]);
            mma_tf32(c[nt][0], c[nt][1], c[nt][2], c[nt][3], a0, a1, a2, a3, bl0, bl1);
        }
    }

    size_t r0 = rb + wid * 16 + g;
    size_t r1 = r0 + 8;
    #pragma unroll
    for (int nt = 0; nt < 8; nt++) {
        int col = cb + nt * 8 + tg * 2;
        *(float2*)&dorsal[r0 * N_OUT + col] = make_float2(c[nt][0], c[nt][1]);
        *(float2*)&dorsal[r1 * N_OUT + col] = make_float2(c[nt][2], c[nt][3]);
    }
}

// ---------------- launch ----------------
extern "C" void kernel_launch(void* const* d_in, const int* in_sizes, int n_in,
                              void* d_out, int out_size)
{
    const float* x     = (const float*)d_in[0];
    const float* h0    = (const float*)d_in[1];
    const float* c0    = (const float*)d_in[2];
    const float* W1    = (const float*)d_in[3];
    const float* b1    = (const float*)d_in[4];
    const float* Wih0  = (const float*)d_in[5];
    const float* Whh0  = (const float*)d_in[6];
    const float* bias0 = (const float*)d_in[7];
    const float* Wih1  = (const float*)d_in[8];
    const float* Whh1  = (const float*)d_in[9];
    const float* bias1 = (const float*)d_in[10];
    const float* Wout  = (const float*)d_in[11];
    const float* bout  = (const float*)d_in[12];

    float* out    = (float*)d_out;
    float* dorsal = out;
    float* rnn    = out + (size_t)ROWS * N_OUT;

    cudaFuncSetAttribute(lstm_kernel, cudaFuncAttributeMaxDynamicSharedMemorySize,
                         LSTM_SMEM_BYTES);

    fc1_mma_kernel<<<ROWS / 128, 256>>>(x, W1, b1);
    bn_stats_kernel<<<1, 256>>>();
    lstm_kernel<<<BB, LSTM_THREADS, LSTM_SMEM_BYTES>>>(h0, c0, Wih0, Whh0, bias0,
                                                       Wih1, Whh1, bias1, rnn);
    out_mma_kernel<<<(ROWS / 128) * (N_OUT / 64), 256>>>(rnn, Wout, bout, dorsal);
}

// round 6
// speedup vs baseline: 1.7502x; 1.0170x over previous
#include <cuda_runtime.h>
#include <cstdint>

#define BB 256
#define SS 512
#define N_IN 2048
#define N_OUT 512
#define HH 30
#define ROWS (BB*SS)   // 131072

// ---------------- device scratch ----------------
__device__ float g_flat[(size_t)ROWS * HH];
__device__ float g_partial[1024 * 64];
__device__ float g_mu[HH];
__device__ float g_rstd[HH];
// pre-converted weights: [n][k][2] = (tf32hi, tf32lo)
__device__ uint32_t g_w1t[32 * N_IN * 2];     // 512 KB
__device__ uint32_t g_wot[N_OUT * 32 * 2];    // 128 KB

// ---------------- helpers ----------------
__device__ __forceinline__ uint32_t cvt_tf32(float f) {
    uint32_t u; asm("cvt.rna.tf32.f32 %0, %1;" : "=r"(u) : "f"(f)); return u;
}
__device__ __forceinline__ void mma_tf32(float& c0, float& c1, float& c2, float& c3,
                                         uint32_t a0, uint32_t a1, uint32_t a2, uint32_t a3,
                                         uint32_t b0, uint32_t b1) {
    asm volatile(
        "mma.sync.aligned.m16n8k8.row.col.f32.tf32.tf32.f32 "
        "{%0,%1,%2,%3},{%4,%5,%6,%7},{%8,%9},{%0,%1,%2,%3};"
        : "+f"(c0), "+f"(c1), "+f"(c2), "+f"(c3)
        : "r"(a0), "r"(a1), "r"(a2), "r"(a3), "r"(b0), "r"(b1));
}
__device__ __forceinline__ float htanh(float x) {
    float r; asm("tanh.approx.f32 %0,%1;" : "=f"(r) : "f"(x)); return r;
}
__device__ __forceinline__ float hsig(float x) {
    return fmaf(htanh(x * 0.5f), 0.5f, 0.5f);
}

// ---------------- prep: convert W1/Wout to tf32 hi/lo interleaved ----------
__global__ __launch_bounds__(256)
void prep_w_kernel(const float* __restrict__ W1, const float* __restrict__ Wout)
{
    int i = blockIdx.x * 256 + threadIdx.x;
    if (i < 32 * N_IN) {
        int k = i >> 5, n = i & 31;
        float w = (n < HH) ? W1[(size_t)k * HH + n] : 0.f;
        uint32_t hb = cvt_tf32(w);
        float lo = w - __uint_as_float(hb);
        g_w1t[(n * N_IN + k) * 2]     = hb;
        g_w1t[(n * N_IN + k) * 2 + 1] = cvt_tf32(lo);
    }
    int j = i - 32 * N_IN;
    if (j >= 0 && j < N_OUT * 32) {
        int n = j >> 5, k = j & 31;
        float w = (k < HH) ? Wout[(size_t)k * N_OUT + n] : 0.f;
        uint32_t hb = cvt_tf32(w);
        float lo = w - __uint_as_float(hb);
        g_wot[(n * 32 + k) * 2]     = hb;
        g_wot[(n * 32 + k) * 2 + 1] = cvt_tf32(lo);
    }
}

// ================= fc1: tf32 mma.sync, double-buffered =================
// C[131072,30] = X @ W1; +bias, ReLU, BN partials.
// smem (floats): A[2][128][36] | B(float2)[2][32][36] | bias[32] | red[2*256]
#define FC1_A_FL (2*128*36)
#define FC1_B_FL (2*32*36*2)
#define FC1_SMEM_BYTES ((FC1_A_FL + FC1_B_FL + 32 + 512) * 4)

__global__ __launch_bounds__(256)
void fc1_mma_kernel(const float* __restrict__ x, const float* __restrict__ b1)
{
    extern __shared__ __align__(16) float sm[];
    float*  a_s    = sm;                               // [2][128][36]
    float2* b_s    = (float2*)(sm + FC1_A_FL);         // [2][32][36]
    float*  bias_s = sm + FC1_A_FL + FC1_B_FL;         // [32]
    float*  red    = bias_s + 32;                      // [2][256]

    const int tid  = threadIdx.x;
    const int wid  = tid >> 5;
    const int lane = tid & 31;
    const int g    = lane >> 2;
    const int tg   = lane & 3;
    const size_t rowBase = (size_t)blockIdx.x * 128;

    if (tid < 32) bias_s[tid] = (tid < HH) ? b1[tid] : 0.f;

    float c[4][4];
    #pragma unroll
    for (int nt = 0; nt < 4; nt++)
        #pragma unroll
        for (int q = 0; q < 4; q++) c[nt][q] = 0.f;

    // A loading: 2 threads/row, each thread 2 float4 (k = akq..akq+3, akq+... ) -> 8 k values
    const int ar  = tid >> 1;            // row 0..127
    const int ak0 = (tid & 1) * 16;      // element base within the 32-k chunk: 0 or 16
    float4 pfa[2];                       // covers k = ak0..ak0+7?  No: 2 float4 = 8 floats
    // Actually thread covers k = ak0/2 .. : use explicit mapping: float4 q covers k = (tid&1)*8 + q*4 .. +3? 
    // Simplify: thread covers 8 consecutive k starting at kb = (tid&1)*8, two float4s. But 32 k per chunk
    // needs 4 thr-halves; with 2 thr/row * 2 float4 = 8 floats -> only 16 k. Use 2 float4 with stride:
    // kb covers [kb, kb+4) and [kb+16, kb+20)? Cleanest: thread loads k in [h*16, h*16+16) via 4 float4?
    // Keep it simple and proven: 2 thr/row, each loads 16 consecutive k (4 float4). That is 2*16=32 k. 
    float4 pfa4[4];
    float4 pfb[2];

    const int kb = (tid & 1) * 16;       // k base: 0 or 16 (16 floats = 4 float4)

    auto prefetch = [&](int j) {
        const float* xp = &x[(rowBase + ar) * (size_t)N_IN + j * 32 + kb];
        #pragma unroll
        for (int q = 0; q < 4; q++) pfa4[q] = *(const float4*)(xp + q * 4);
        const float4* wb = (const float4*)g_w1t;    // per n: N_IN/2 float4; chunk j -> 16 float4
        #pragma unroll
        for (int q = 0; q < 2; q++) {
            int idx = q * 256 + tid;                // 0..511
            int n = idx >> 4, fi = idx & 15;
            pfb[q] = wb[(size_t)n * (N_IN / 2) + j * 16 + fi];
        }
    };
    auto store_stage = [&](int st) {
        float* ap = &a_s[st * 4608 + ar * 36 + kb];
        #pragma unroll
        for (int q = 0; q < 4; q++) {
            ap[q*4+0] = __uint_as_float(cvt_tf32(pfa4[q].x));
            ap[q*4+1] = __uint_as_float(cvt_tf32(pfa4[q].y));
            ap[q*4+2] = __uint_as_float(cvt_tf32(pfa4[q].z));
            ap[q*4+3] = __uint_as_float(cvt_tf32(pfa4[q].w));
        }
        #pragma unroll
        for (int q = 0; q < 2; q++) {
            int idx = q * 256 + tid;
            int n = idx >> 4, fi = idx & 15;
            *(float4*)&b_s[st * 1152 + n * 36 + fi * 2] = pfb[q];
        }
    };

    prefetch(0);
    store_stage(0);
    __syncthreads();
    prefetch(1);

    const int mr = wid * 16;
    for (int j = 0; j < 64; j++) {
        const int cur = j & 1, nxt = cur ^ 1;
        if (j < 63) store_stage(nxt);
        if (j < 62) prefetch(j + 2);
        const float* ab = &a_s[cur * 4608];
        const float2* bbp = &b_s[cur * 1152];
        #pragma unroll
        for (int ks = 0; ks < 4; ks++) {
            const int k0 = ks * 8;
            uint32_t a0 = __float_as_uint(ab[(mr + g    ) * 36 + k0 + tg    ]);
            uint32_t a1 = __float_as_uint(ab[(mr + g + 8) * 36 + k0 + tg    ]);
            uint32_t a2 = __float_as_uint(ab[(mr + g    ) * 36 + k0 + tg + 4]);
            uint32_t a3 = __float_as_uint(ab[(mr + g + 8) * 36 + k0 + tg + 4]);
            #pragma unroll
            for (int nt = 0; nt < 4; nt++) {
                float2 f0 = bbp[(nt*8 + g) * 36 + k0 + tg    ];
                float2 f1 = bbp[(nt*8 + g) * 36 + k0 + tg + 4];
                mma_tf32(c[nt][0], c[nt][1], c[nt][2], c[nt][3], a0, a1, a2, a3,
                         __float_as_uint(f0.x), __float_as_uint(f1.x));
                mma_tf32(c[nt][0], c[nt][1], c[nt][2], c[nt][3], a0, a1, a2, a3,
                         __float_as_uint(f0.y), __float_as_uint(f1.y));
            }
        }
        __syncthreads();
    }

    // epilogue: bias + ReLU + store + BN partials
    size_t r0 = rowBase + wid * 16 + g;
    size_t r1 = r0 + 8;
    #pragma unroll
    for (int nt = 0; nt < 4; nt++) {
        int col = nt * 8 + tg * 2;
        float v00 = 0.f, v01 = 0.f, v10 = 0.f, v11 = 0.f;
        if (col < HH) {
            v00 = fmaxf(c[nt][0] + bias_s[col],     0.f);
            v01 = fmaxf(c[nt][1] + bias_s[col + 1], 0.f);
            v10 = fmaxf(c[nt][2] + bias_s[col],     0.f);
            v11 = fmaxf(c[nt][3] + bias_s[col + 1], 0.f);
            *(float2*)&g_flat[r0 * HH + col] = make_float2(v00, v01);
            *(float2*)&g_flat[r1 * HH + col] = make_float2(v10, v11);
        }
        float s0 = v00 + v10, q0 = v00 * v00 + v10 * v10;
        float s1 = v01 + v11, q1 = v01 * v01 + v11 * v11;
        #pragma unroll
        for (int off = 4; off < 32; off <<= 1) {
            s0 += __shfl_xor_sync(0xffffffffu, s0, off);
            q0 += __shfl_xor_sync(0xffffffffu, q0, off);
            s1 += __shfl_xor_sync(0xffffffffu, s1, off);
            q1 += __shfl_xor_sync(0xffffffffu, q1, off);
        }
        if (g == 0) {
            red[(col    ) * 8 + wid]       = s0;
            red[(col + 1) * 8 + wid]       = s1;
            red[256 + (col    ) * 8 + wid] = q0;
            red[256 + (col + 1) * 8 + wid] = q1;
        }
    }
    __syncthreads();
    if (tid < HH) {
        float s = 0.f, q = 0.f;
        #pragma unroll
        for (int w = 0; w < 8; w++) { s += red[tid * 8 + w]; q += red[256 + tid * 8 + w]; }
        g_partial[blockIdx.x * 60 + tid]      = s;
        g_partial[blockIdx.x * 60 + 30 + tid] = q;
    }
}

// ---------------- BN finalize ----------------
__global__ void bn_stats_kernel()
{
    __shared__ float rs[2][HH][9];
    int c = threadIdx.x & 31;
    int g = threadIdx.x >> 5;   // 0..7
    if (c < HH) {
        float s = 0.f, q = 0.f;
        for (int p = g; p < 1024; p += 8) {
            s += g_partial[p * 60 + c];
            q += g_partial[p * 60 + 30 + c];
        }
        rs[0][c][g] = s; rs[1][c][g] = q;
    }
    __syncthreads();
    if (threadIdx.x < HH) {
        float s = 0.f, q = 0.f;
        #pragma unroll
        for (int g2 = 0; g2 < 8; g2++) { s += rs[0][threadIdx.x][g2]; q += rs[1][threadIdx.x][g2]; }
        const float n = (float)ROWS;
        float mu  = s / n;
        float var = q / n - mu * mu;
        g_mu[threadIdx.x]   = mu;
        g_rstd[threadIdx.x] = rsqrtf(var + 1e-5f);
    }
}

// ---------------- LSTM (scalar + MUFU tanh) ----------------
#define LSTM_THREADS 256
#define LSTM_SMEM_FLOATS (SS*32 + 32 + 32 + 32 + 128 + 128 + 32 + 32)
#define LSTM_SMEM_BYTES  (LSTM_SMEM_FLOATS * 4)

__device__ __forceinline__ float dot_step(const float* __restrict__ xv,
                                          const float* __restrict__ hv,
                                          const float (&wi)[32], const float (&wh)[32],
                                          float bj)
{
    const float4* x4 = (const float4*)xv;
    const float4* h4 = (const float4*)hv;
    float a0 = bj, a1 = 0.f, a2 = 0.f, a3 = 0.f;
    float b0 = 0.f, b1 = 0.f, b2 = 0.f, b3 = 0.f;
    #pragma unroll
    for (int q = 0; q < 8; q++) {
        float4 xq = x4[q];
        a0 += wi[4*q+0] * xq.x; a1 += wi[4*q+1] * xq.y;
        a2 += wi[4*q+2] * xq.z; a3 += wi[4*q+3] * xq.w;
        float4 hq = h4[q];
        b0 += wh[4*q+0] * hq.x; b1 += wh[4*q+1] * hq.y;
        b2 += wh[4*q+2] * hq.z; b3 += wh[4*q+3] * hq.w;
    }
    return ((a0 + a1) + (a2 + a3)) + ((b0 + b1) + (b2 + b3));
}

__global__ __launch_bounds__(LSTM_THREADS, 2)
void lstm_kernel(const float* __restrict__ h0, const float* __restrict__ c0,
                 const float* __restrict__ Wih0, const float* __restrict__ Whh0,
                 const float* __restrict__ bias0,
                 const float* __restrict__ Wih1, const float* __restrict__ Whh1,
                 const float* __restrict__ bias1,
                 float* __restrict__ rnn_out)
{
    extern __shared__ __align__(16) float lsm[];
    float* xs    = lsm;                    // [512][32]
    float* h0s   = lsm + SS * 32;          // [32]
    float* h1s   = h0s + 32;               // [32]
    float* y0s   = h1s + 32;               // [32]
    float* z0s   = y0s + 32;               // [128]
    float* z1s   = z0s + 128;              // [128]
    float* mus   = z1s + 128;              // [32]
    float* rstds = mus + 32;               // [32]

    const int tid = threadIdx.x;
    const int b   = blockIdx.x;

    if (tid < 32) {
        mus[tid]   = (tid < HH) ? g_mu[tid]   : 0.f;
        rstds[tid] = (tid < HH) ? g_rstd[tid] : 0.f;
        h0s[tid] = (tid < HH) ? h0[b * HH + tid]            : 0.f;
        h1s[tid] = (tid < HH) ? h0[BB * HH + b * HH + tid]  : 0.f;
        y0s[tid] = 0.f;
    }
    __syncthreads();

    const float* fb = g_flat + (size_t)b * (SS * HH);
    for (int i = tid; i < SS * 32; i += LSTM_THREADS) {
        int s = i >> 5, k = i & 31;
        xs[i] = (k < HH) ? (fb[s * HH + k] - mus[k]) * rstds[k] : 0.f;
    }

    float wi[32], wh[32];
    float bj = 0.f;
    #pragma unroll
    for (int k = 0; k < 32; k++) { wi[k] = 0.f; wh[k] = 0.f; }
    if (tid < 120) {
        #pragma unroll
        for (int k = 0; k < HH; k++) {
            wi[k] = Wih0[tid * HH + k];
            wh[k] = Whh0[tid * HH + k];
        }
        bj = bias0[tid];
    } else if (tid >= 128 && tid < 248) {
        int j = tid - 128;
        #pragma unroll
        for (int k = 0; k < HH; k++) {
            wi[k] = Wih1[j * HH + k];
            wh[k] = Whh1[j * HH + k];
        }
        bj = bias1[j];
    }

    float creg = 0.f;
    if (tid < HH)                          creg = c0[b * HH + tid];
    else if (tid >= 128 && tid < 128+HH)   creg = c0[BB * HH + b * HH + (tid - 128)];

    __syncthreads();

    for (int t = 0; t <= SS; t++) {
        if (t < SS && tid < 120) {
            z0s[tid] = dot_step(xs + t * 32, h0s, wi, wh, bj);
        } else if (t >= 1 && tid >= 128 && tid < 248) {
            z1s[tid - 128] = dot_step(y0s, h1s, wi, wh, bj);
        }
        __syncthreads();
        if (t < SS && tid < HH) {
            float ig = hsig(z0s[tid]);
            float fg = hsig(z0s[30 + tid]);
            float gg = htanh(z0s[60 + tid]);
            float og = hsig(z0s[90 + tid]);
            creg = fg * creg + ig * gg;
            float hh = og * htanh(creg);
            h0s[tid] = hh;
            y0s[tid] = hh;
        } else if (t >= 1 && tid >= 128 && tid < 128 + HH) {
            int u = tid - 128;
            float ig = hsig(z1s[u]);
            float fg = hsig(z1s[30 + u]);
            float gg = htanh(z1s[60 + u]);
            float og = hsig(z1s[90 + u]);
            creg = fg * creg + ig * gg;
            float hh = og * htanh(creg);
            h1s[u] = hh;
            rnn_out[((size_t)b * SS + (t - 1)) * HH + u] = hh;
        }
        __syncthreads();
    }
}

// ================= output GEMM: tf32 mma.sync, 128x128 tiles =================
// smem: A[128][36] floats | B(float2)[128][36]
#define OG_A_FL (128*36)
#define OG_B_FL (128*36*2)
#define OG_SMEM_BYTES ((OG_A_FL + OG_B_FL) * 4)

__global__ __launch_bounds__(256)
void out_mma_kernel(const float* __restrict__ rnn, const float* __restrict__ bout,
                    float* __restrict__ dorsal)
{
    extern __shared__ __align__(16) float sm[];
    float*  a_s = sm;                      // [128][36]
    float2* b_s = (float2*)(sm + OG_A_FL); // [128][36]

    const int tid  = threadIdx.x;
    const int wid  = tid >> 5;
    const int lane = tid & 31;
    const int g    = lane >> 2;
    const int tg   = lane & 3;
    const size_t rb = (size_t)(blockIdx.x >> 2) * 128;
    const int cb    = (blockIdx.x & 3) * 128;

    // A: rnn rows, k padded 30->32, tf32
    for (int i = tid; i < 128 * 32; i += 256) {
        int r = i >> 5, k = i & 31;
        float v = (k < HH) ? rnn[(rb + r) * HH + k] : 0.f;
        a_s[r * 36 + k] = __uint_as_float(cvt_tf32(v));
    }
    // B: preconverted g_wot[n][k][2] -> smem float2[n][k]
    {
        const float4* wb = (const float4*)g_wot;   // 16 float4 per n
        #pragma unroll
        for (int q = 0; q < 8; q++) {
            int idx = q * 256 + tid;               // 0..2047
            int n = idx >> 4, fi = idx & 15;
            float4 v = wb[(size_t)(cb + n) * 16 + fi];
            *(float4*)&b_s[n * 36 + fi * 2] = v;
        }
    }

    float c[16][4];
    #pragma unroll
    for (int nt = 0; nt < 16; nt++) {
        float bv0 = bout[cb + nt * 8 + tg * 2];
        float bv1 = bout[cb + nt * 8 + tg * 2 + 1];
        c[nt][0] = bv0; c[nt][1] = bv1; c[nt][2] = bv0; c[nt][3] = bv1;
    }
    __syncthreads();

    const int mr = wid * 16;
    #pragma unroll
    for (int ks = 0; ks < 4; ks++) {
        const int k0 = ks * 8;
        uint32_t a0 = __float_as_uint(a_s[(mr + g    ) * 36 + k0 + tg    ]);
        uint32_t a1 = __float_as_uint(a_s[(mr + g + 8) * 36 + k0 + tg    ]);
        uint32_t a2 = __float_as_uint(a_s[(mr + g    ) * 36 + k0 + tg + 4]);
        uint32_t a3 = __float_as_uint(a_s[(mr + g + 8) * 36 + k0 + tg + 4]);
        #pragma unroll
        for (int nt = 0; nt < 16; nt++) {
            float2 f0 = b_s[(nt*8 + g) * 36 + k0 + tg    ];
            float2 f1 = b_s[(nt*8 + g) * 36 + k0 + tg + 4];
            mma_tf32(c[nt][0], c[nt][1], c[nt][2], c[nt][3], a0, a1, a2, a3,
                     __float_as_uint(f0.x), __float_as_uint(f1.x));
            mma_tf32(c[nt][0], c[nt][1], c[nt][2], c[nt][3], a0, a1, a2, a3,
                     __float_as_uint(f0.y), __float_as_uint(f1.y));
        }
    }

    size_t r0 = rb + wid * 16 + g;
    size_t r1 = r0 + 8;
    #pragma unroll
    for (int nt = 0; nt < 16; nt++) {
        int col = cb + nt * 8 + tg * 2;
        *(float2*)&dorsal[r0 * N_OUT + col] = make_float2(c[nt][0], c[nt][1]);
        *(float2*)&dorsal[r1 * N_OUT + col] = make_float2(c[nt][2], c[nt][3]);
    }
}

// ---------------- launch ----------------
extern "C" void kernel_launch(void* const* d_in, const int* in_sizes, int n_in,
                              void* d_out, int out_size)
{
    const float* x     = (const float*)d_in[0];
    const float* h0    = (const float*)d_in[1];
    const float* c0    = (const float*)d_in[2];
    const float* W1    = (const float*)d_in[3];
    const float* b1    = (const float*)d_in[4];
    const float* Wih0  = (const float*)d_in[5];
    const float* Whh0  = (const float*)d_in[6];
    const float* bias0 = (const float*)d_in[7];
    const float* Wih1  = (const float*)d_in[8];
    const float* Whh1  = (const float*)d_in[9];
    const float* bias1 = (const float*)d_in[10];
    const float* Wout  = (const float*)d_in[11];
    const float* bout  = (const float*)d_in[12];

    float* out    = (float*)d_out;
    float* dorsal = out;
    float* rnn    = out + (size_t)ROWS * N_OUT;

    cudaFuncSetAttribute(fc1_mma_kernel, cudaFuncAttributeMaxDynamicSharedMemorySize,
                         FC1_SMEM_BYTES);
    cudaFuncSetAttribute(out_mma_kernel, cudaFuncAttributeMaxDynamicSharedMemorySize,
                         OG_SMEM_BYTES);
    cudaFuncSetAttribute(lstm_kernel, cudaFuncAttributeMaxDynamicSharedMemorySize,
                         LSTM_SMEM_BYTES);

    prep_w_kernel<<<(32 * N_IN + N_OUT * 32) / 256, 256>>>(W1, Wout);
    fc1_mma_kernel<<<ROWS / 128, 256, FC1_SMEM_BYTES>>>(x, b1);
    bn_stats_kernel<<<1, 256>>>();
    lstm_kernel<<<BB, LSTM_THREADS, LSTM_SMEM_BYTES>>>(h0, c0, Wih0, Whh0, bias0,
                                                       Wih1, Whh1, bias1, rnn);
    out_mma_kernel<<<(ROWS / 128) * (N_OUT / 128), 256, OG_SMEM_BYTES>>>(rnn, bout, dorsal);
}